// round 9
// baseline (speedup 1.0000x reference)
#include <cuda_runtime.h>

#define H_IMG 1080
#define W_IMG 1920
#define GY 16
#define GX 16
#define GW 8
#define NPIX (H_IMG * W_IMG)

#define BX 384                      // threads = output float4 elements per block
#define PXB 128                     // pixels per block
#define BLK_PER_ROW (W_IMG / PXB)   // 15
#define NC 3                        // x-cells per strip
#define NCELL (NC * GW)             // 24

#define SX (15.0f / 1919.0f)
#define SY (15.0f / 1079.0f)

__global__ __launch_bounds__(BX) void bilateral_grid_kernel(
    const float* __restrict__ rgb,
    const float* __restrict__ grids,
    const int*   __restrict__ idxp,
    float*       __restrict__ out)
{
    // slab[(cell*3+chunk)*2 + {0,1}] = {val4, dz4}  (fp32, 2304B)
    __shared__ __align__(16) float4 slab[NCELL * 3 * 2];
    // xtab[q] = {wx, o0(bits), o1(bits), -}  where o = x_local * 24 * 2
    __shared__ __align__(16) float4 xtab[PXB];

    const int tid   = threadIdx.x;
    const int row   = blockIdx.y;
    const int xpix0 = blockIdx.x * PXB;
    const int xbase = (int)((float)xpix0 * SX);

    // ---- rgb prefetch (3 lanes per pixel broadcast the same line) ----
    const int q = tid / 3;
    const int c = tid - 3 * q;
    const int n = row * W_IMG + xpix0 + q;
    float r = __ldcs(rgb + n);
    float g = __ldcs(rgb + NPIX + n);
    float b = __ldcs(rgb + 2 * NPIX + n);

    if (tid < NCELL * 3) {
        // ---- slab build: y-lerp + z-delta, 72 threads ----
        const float* grid = grids + (size_t)idxp[0] * (GY * GX * GW * 12);
        float gyv = (float)row * SY;
        float fy  = floorf(gyv);
        float wy  = gyv - fy;
        int y0 = min((int)fy, GY - 1);
        int y1 = min(y0 + 1, GY - 1);
        float wy0 = 1.0f - wy, wy1 = wy;

        int cell = tid / 3;
        int c4   = tid - cell * 3;
        int xq   = cell / GW;
        int zq   = cell - xq * GW;
        int zq1  = min(zq + 1, GW - 1);
        int xc   = min(xbase + xq, GX - 1);

        const float4* p00 = reinterpret_cast<const float4*>(
            grid + ((size_t)(y0 * GX + xc) * GW + zq)  * 12) + c4;
        const float4* p10 = reinterpret_cast<const float4*>(
            grid + ((size_t)(y1 * GX + xc) * GW + zq)  * 12) + c4;
        const float4* p01 = reinterpret_cast<const float4*>(
            grid + ((size_t)(y0 * GX + xc) * GW + zq1) * 12) + c4;
        const float4* p11 = reinterpret_cast<const float4*>(
            grid + ((size_t)(y1 * GX + xc) * GW + zq1) * 12) + c4;
        float4 a0 = __ldg(p00), a1 = __ldg(p10);
        float4 b0 = __ldg(p01), b1 = __ldg(p11);

        float4 v, nx;
        v.x  = wy0 * a0.x + wy1 * a1.x;  v.y  = wy0 * a0.y + wy1 * a1.y;
        v.z  = wy0 * a0.z + wy1 * a1.z;  v.w  = wy0 * a0.w + wy1 * a1.w;
        nx.x = wy0 * b0.x + wy1 * b1.x;  nx.y = wy0 * b0.y + wy1 * b1.y;
        nx.z = wy0 * b0.z + wy1 * b1.z;  nx.w = wy0 * b0.w + wy1 * b1.w;

        slab[tid * 2]     = v;
        slab[tid * 2 + 1] = make_float4(nx.x - v.x, nx.y - v.y,
                                        nx.z - v.z, nx.w - v.w);
    } else if (tid >= 256) {
        // ---- x-table build: 128 threads ----
        int qq = tid - 256;
        int x  = xpix0 + qq;
        float gxv = (float)x * SX;
        float fx  = floorf(gxv);
        float wx  = gxv - fx;
        int xc0 = min((int)fx, GX - 1);
        int xc1 = min(xc0 + 1, GX - 1);
        int o0 = (xc0 - xbase) * (GW * 3 * 2);   // float4 index of cell column
        int o1 = (xc1 - xbase) * (GW * 3 * 2);
        xtab[qq] = make_float4(wx, __int_as_float(o0), __int_as_float(o1), 0.0f);
    }
    __syncthreads();

    // ---- hot path: one output float4 per thread ----
    float gray = 0.299f * r + 0.587f * g + 0.114f * b;
    float gz = __saturatef(gray) * 7.0f;     // in [0,7]
    float fz = floorf(gz);
    float wz = gz - fz;
    int z0 = (int)fz;                        // 0..7, no clamps needed

    float4 xe = xtab[q];
    float wx  = xe.x;
    int zc = (z0 * 3 + c) * 2;
    int ia = __float_as_int(xe.y) + zc;
    int ib = __float_as_int(xe.z) + zc;

    float4 va = slab[ia],     da = slab[ia + 1];
    float4 vb = slab[ib],     db = slab[ib + 1];

    float w0 = 1.0f - wx;
    float4 a4;
    a4.x = fmaf(wx, fmaf(wz, db.x, vb.x), w0 * fmaf(wz, da.x, va.x));
    a4.y = fmaf(wx, fmaf(wz, db.y, vb.y), w0 * fmaf(wz, da.y, va.y));
    a4.z = fmaf(wx, fmaf(wz, db.z, vb.z), w0 * fmaf(wz, da.z, va.z));
    a4.w = fmaf(wx, fmaf(wz, db.w, vb.w), w0 * fmaf(wz, da.w, va.w));

    const size_t base3 = (size_t)(row * W_IMG + xpix0) * 3;

    // affine: warp writes 512B contiguous
    __stcs(reinterpret_cast<float4*>(out) + base3 + tid, a4);

    // res: warp writes 128B contiguous (element (p, c) == row c of p's matrix)
    float resv = fmaf(a4.x, r, fmaf(a4.y, g, fmaf(a4.z, b, a4.w)));
    __stcs(out + (size_t)12 * NPIX + base3 + tid, resv);
}

extern "C" void kernel_launch(void* const* d_in, const int* in_sizes, int n_in,
                              void* d_out, int out_size) {
    const float* rgb   = (const float*)d_in[0];
    const float* grids = (const float*)d_in[1];
    const int*   idx   = (const int*)d_in[2];
    float* out = (float*)d_out;

    dim3 grid(BLK_PER_ROW, H_IMG);   // 15 x 1080
    bilateral_grid_kernel<<<grid, BX>>>(rgb, grids, idx, out);
}

// round 10
// speedup vs baseline: 1.2569x; 1.2569x over previous
#include <cuda_runtime.h>
#include <cuda_fp16.h>

#define H_IMG 1080
#define W_IMG 1920
#define GY 16
#define GX 16
#define GW 8
#define NPIX (H_IMG * W_IMG)

#define BX 384                      // threads = output float4 elements per block
#define PXB 128                     // pixels per block
#define BLK_PER_ROW (W_IMG / PXB)   // 15
#define NC 3                        // x-cells per strip
#define NCELL (NC * GW)             // 24

#define SX (15.0f / 1919.0f)
#define SY (15.0f / 1079.0f)

__device__ __forceinline__ float2 h2f(unsigned u) {
    __half2 h;
    *reinterpret_cast<unsigned*>(&h) = u;
    return __half22float2(h);
}
__device__ __forceinline__ unsigned f2h2(float a, float b) {
    __half2 h = __floats2half2_rn(a, b);
    return *reinterpret_cast<unsigned*>(&h);
}

__global__ __launch_bounds__(BX) void bilateral_grid_kernel(
    const float* __restrict__ rgb,
    const float* __restrict__ grids,
    const int*   __restrict__ idxp,
    float*       __restrict__ out)
{
    // slabh[cell*3+c] = uint4 { h2(v0,v1), h2(v2,v3), h2(d0,d1), h2(d2,d3) }
    // 72 entries * 16B = 1152B
    __shared__ __align__(16) uint4 slabh[NCELL * 3];
    // xtab[q] = {wx, o0(bits), o1(bits), -}; o = x-column start (uint4 index)
    __shared__ __align__(16) float4 xtab[PXB];

    const int tid   = threadIdx.x;
    const int row   = blockIdx.y;
    const int xpix0 = blockIdx.x * PXB;
    const int xbase = (int)((float)xpix0 * SX);

    // ---- rgb prefetch (3 lanes per pixel share the line) ----
    const int q = tid / 3;
    const int c = tid - 3 * q;
    const int n = row * W_IMG + xpix0 + q;
    float r = __ldcs(rgb + n);
    float g = __ldcs(rgb + NPIX + n);
    float b = __ldcs(rgb + 2 * NPIX + n);

    if (tid < NCELL * 3) {
        // ---- slab build: y-lerp + z-delta, packed fp16. 72 threads ----
        const float* grid = grids + (size_t)idxp[0] * (GY * GX * GW * 12);
        float gyv = (float)row * SY;
        float fy  = floorf(gyv);
        float wy  = gyv - fy;
        int y0 = min((int)fy, GY - 1);
        int y1 = min(y0 + 1, GY - 1);
        float wy0 = 1.0f - wy, wy1 = wy;

        int cell = tid / 3;
        int c4   = tid - cell * 3;
        int xq   = cell / GW;
        int zq   = cell - xq * GW;
        int zq1  = min(zq + 1, GW - 1);
        int xc   = min(xbase + xq, GX - 1);

        float4 a0 = __ldg(reinterpret_cast<const float4*>(
            grid + ((size_t)(y0 * GX + xc) * GW + zq)  * 12) + c4);
        float4 a1 = __ldg(reinterpret_cast<const float4*>(
            grid + ((size_t)(y1 * GX + xc) * GW + zq)  * 12) + c4);
        float4 b0 = __ldg(reinterpret_cast<const float4*>(
            grid + ((size_t)(y0 * GX + xc) * GW + zq1) * 12) + c4);
        float4 b1 = __ldg(reinterpret_cast<const float4*>(
            grid + ((size_t)(y1 * GX + xc) * GW + zq1) * 12) + c4);

        float4 v, nx;
        v.x  = wy0 * a0.x + wy1 * a1.x;  v.y  = wy0 * a0.y + wy1 * a1.y;
        v.z  = wy0 * a0.z + wy1 * a1.z;  v.w  = wy0 * a0.w + wy1 * a1.w;
        nx.x = wy0 * b0.x + wy1 * b1.x;  nx.y = wy0 * b0.y + wy1 * b1.y;
        nx.z = wy0 * b0.z + wy1 * b1.z;  nx.w = wy0 * b0.w + wy1 * b1.w;

        uint4 pk;
        pk.x = f2h2(v.x, v.y);
        pk.y = f2h2(v.z, v.w);
        pk.z = f2h2(nx.x - v.x, nx.y - v.y);
        pk.w = f2h2(nx.z - v.z, nx.w - v.w);
        slabh[tid] = pk;
    } else if (tid >= 256) {
        // ---- x-table build: 128 threads ----
        int qq = tid - 256;
        int x  = xpix0 + qq;
        float gxv = (float)x * SX;
        float fx  = floorf(gxv);
        float wx  = gxv - fx;
        int xc0 = min((int)fx, GX - 1);
        int xc1 = min(xc0 + 1, GX - 1);
        int o0 = (xc0 - xbase) * (GW * 3);    // uint4 index of x-column start
        int o1 = (xc1 - xbase) * (GW * 3);
        xtab[qq] = make_float4(wx, __int_as_float(o0), __int_as_float(o1), 0.0f);
    }
    __syncthreads();

    // ---- hot path: one output float4 per thread ----
    float gray = 0.299f * r + 0.587f * g + 0.114f * b;
    float gz = __saturatef(gray) * 7.0f;     // [0,7]
    float fz = floorf(gz);
    float wz = gz - fz;
    int z0 = (int)fz;

    float4 xe = xtab[q];
    float wx  = xe.x;
    int zc = z0 * 3 + c;
    uint4 ua = slabh[__float_as_int(xe.y) + zc];   // corner x0: val+dz
    uint4 ub = slabh[__float_as_int(xe.z) + zc];   // corner x1: val+dz

    float w0 = 1.0f - wx;
    float4 a4;
    {
        float2 va01 = h2f(ua.x), va23 = h2f(ua.y);
        float2 da01 = h2f(ua.z), da23 = h2f(ua.w);
        float2 vb01 = h2f(ub.x), vb23 = h2f(ub.y);
        float2 db01 = h2f(ub.z), db23 = h2f(ub.w);
        a4.x = fmaf(wx, fmaf(wz, db01.x, vb01.x), w0 * fmaf(wz, da01.x, va01.x));
        a4.y = fmaf(wx, fmaf(wz, db01.y, vb01.y), w0 * fmaf(wz, da01.y, va01.y));
        a4.z = fmaf(wx, fmaf(wz, db23.x, vb23.x), w0 * fmaf(wz, da23.x, va23.x));
        a4.w = fmaf(wx, fmaf(wz, db23.y, vb23.y), w0 * fmaf(wz, da23.y, va23.y));
    }

    const size_t base3 = (size_t)(row * W_IMG + xpix0) * 3;

    // affine: block writes 6KB contiguous
    __stcs(reinterpret_cast<float4*>(out) + base3 + tid, a4);

    // res: block writes 1.5KB contiguous
    float resv = fmaf(a4.x, r, fmaf(a4.y, g, fmaf(a4.z, b, a4.w)));
    __stcs(out + (size_t)12 * NPIX + base3 + tid, resv);
}

extern "C" void kernel_launch(void* const* d_in, const int* in_sizes, int n_in,
                              void* d_out, int out_size) {
    const float* rgb   = (const float*)d_in[0];
    const float* grids = (const float*)d_in[1];
    const int*   idx   = (const int*)d_in[2];
    float* out = (float*)d_out;

    dim3 grid(BLK_PER_ROW, H_IMG);   // 15 x 1080
    bilateral_grid_kernel<<<grid, BX>>>(rgb, grids, idx, out);
}

// round 11
// speedup vs baseline: 1.5891x; 1.2643x over previous
#include <cuda_runtime.h>
#include <cuda_fp16.h>

#define H_IMG 1080
#define W_IMG 1920
#define GY 16
#define GX 16
#define GW 8
#define NPIX (H_IMG * W_IMG)

#define BX 384                      // threads per block
#define PXB 256                     // pixels per block (2 elements/thread)
#define NC 4                        // x-cells per 256-px strip
#define NCELL (NC * GW)             // 32 cells, 96 slab entries

#define SX (15.0f / 1919.0f)
#define SY (15.0f / 1079.0f)

__device__ __forceinline__ float2 h2f(unsigned u) {
    __half2 h;
    *reinterpret_cast<unsigned*>(&h) = u;
    return __half22float2(h);
}
__device__ __forceinline__ unsigned f2h2(float a, float b) {
    __half2 h = __floats2half2_rn(a, b);
    return *reinterpret_cast<unsigned*>(&h);
}

__global__ __launch_bounds__(BX) void bilateral_grid_kernel(
    const float* __restrict__ rgb,
    const float* __restrict__ grids,
    const int*   __restrict__ idxp,
    float*       __restrict__ out)
{
    // slabh[cell*3+c] = uint4 { h2(v0,v1), h2(v2,v3), h2(d0,d1), h2(d2,d3) }
    __shared__ __align__(16) uint4 slabh[NCELL * 3];       // 96 * 16B
    // xtab[q] = {wx, o0(bits), o1(bits), -}; o = x-column start (uint4 idx)
    __shared__ __align__(16) float4 xtab[PXB];             // 256 * 16B

    const int tid   = threadIdx.x;
    const int row   = blockIdx.y;
    const int xpix0 = blockIdx.x * PXB;
    const int xbase = (int)((float)xpix0 * SX);

    // thread's two elements: e0 = tid, e1 = tid + 384 (same chunk c, q1 = q0+128)
    const int q0 = tid / 3;
    const int c  = tid - 3 * q0;
    const int q1 = q0 + 128;
    const bool has1 = (xpix0 + q1 < W_IMG);   // last block in row covers 128 px

    // ---- rgb prefetch for both pixels ----
    const int n0 = row * W_IMG + xpix0 + q0;
    float r0 = __ldcs(rgb + n0);
    float g0 = __ldcs(rgb + NPIX + n0);
    float b0 = __ldcs(rgb + 2 * NPIX + n0);
    float r1 = 0.f, g1 = 0.f, b1 = 0.f;
    if (has1) {
        r1 = __ldcs(rgb + n0 + 128);
        g1 = __ldcs(rgb + NPIX + n0 + 128);
        b1 = __ldcs(rgb + 2 * NPIX + n0 + 128);
    }

    if (tid < NCELL * 3) {
        // ---- slab build: y-lerp + z-delta, packed fp16. 96 threads ----
        const float* grid = grids + (size_t)idxp[0] * (GY * GX * GW * 12);
        float gyv = (float)row * SY;
        float fy  = floorf(gyv);
        float wy  = gyv - fy;
        int y0 = min((int)fy, GY - 1);
        int y1 = min(y0 + 1, GY - 1);
        float wy0 = 1.0f - wy, wy1 = wy;

        int cell = tid / 3;
        int c4   = tid - cell * 3;
        int xq   = cell / GW;
        int zq   = cell - xq * GW;
        int zq1  = min(zq + 1, GW - 1);
        int xc   = min(xbase + xq, GX - 1);

        float4 a0 = __ldg(reinterpret_cast<const float4*>(
            grid + ((size_t)(y0 * GX + xc) * GW + zq)  * 12) + c4);
        float4 a1 = __ldg(reinterpret_cast<const float4*>(
            grid + ((size_t)(y1 * GX + xc) * GW + zq)  * 12) + c4);
        float4 bb0 = __ldg(reinterpret_cast<const float4*>(
            grid + ((size_t)(y0 * GX + xc) * GW + zq1) * 12) + c4);
        float4 bb1 = __ldg(reinterpret_cast<const float4*>(
            grid + ((size_t)(y1 * GX + xc) * GW + zq1) * 12) + c4);

        float4 v, nx;
        v.x  = wy0 * a0.x  + wy1 * a1.x;   v.y  = wy0 * a0.y  + wy1 * a1.y;
        v.z  = wy0 * a0.z  + wy1 * a1.z;   v.w  = wy0 * a0.w  + wy1 * a1.w;
        nx.x = wy0 * bb0.x + wy1 * bb1.x;  nx.y = wy0 * bb0.y + wy1 * bb1.y;
        nx.z = wy0 * bb0.z + wy1 * bb1.z;  nx.w = wy0 * bb0.w + wy1 * bb1.w;

        uint4 pk;
        pk.x = f2h2(v.x, v.y);
        pk.y = f2h2(v.z, v.w);
        pk.z = f2h2(nx.x - v.x, nx.y - v.y);
        pk.w = f2h2(nx.z - v.z, nx.w - v.w);
        slabh[tid] = pk;
    } else if (tid >= 128) {
        // ---- x-table build: 256 threads (tid 128..383) ----
        int qq = tid - 128;
        int x  = xpix0 + qq;
        float gxv = (float)x * SX;
        float fx  = floorf(gxv);
        float wx  = gxv - fx;
        int xc0 = min((int)fx, GX - 1);
        int xc1 = min(xc0 + 1, GX - 1);
        int o0 = (xc0 - xbase) * (GW * 3);
        int o1 = (xc1 - xbase) * (GW * 3);
        xtab[qq] = make_float4(wx, __int_as_float(o0), __int_as_float(o1), 0.0f);
    }
    __syncthreads();

    const size_t base3 = (size_t)(row * W_IMG + xpix0) * 3;
    float4* aff = reinterpret_cast<float4*>(out) + base3;
    float*  res = out + (size_t)12 * NPIX + base3;

    // ================= element 0 =================
    {
        float gray = 0.299f * r0 + 0.587f * g0 + 0.114f * b0;
        float gz = __saturatef(gray) * 7.0f;
        float fz = floorf(gz);
        float wz = gz - fz;
        int z0 = (int)fz;

        float4 xe = xtab[q0];
        float wx  = xe.x;
        int zc = z0 * 3 + c;
        uint4 ua = slabh[__float_as_int(xe.y) + zc];
        uint4 ub = slabh[__float_as_int(xe.z) + zc];

        float w0 = 1.0f - wx;
        float2 va01 = h2f(ua.x), va23 = h2f(ua.y);
        float2 da01 = h2f(ua.z), da23 = h2f(ua.w);
        float2 vb01 = h2f(ub.x), vb23 = h2f(ub.y);
        float2 db01 = h2f(ub.z), db23 = h2f(ub.w);
        float4 a4;
        a4.x = fmaf(wx, fmaf(wz, db01.x, vb01.x), w0 * fmaf(wz, da01.x, va01.x));
        a4.y = fmaf(wx, fmaf(wz, db01.y, vb01.y), w0 * fmaf(wz, da01.y, va01.y));
        a4.z = fmaf(wx, fmaf(wz, db23.x, vb23.x), w0 * fmaf(wz, da23.x, va23.x));
        a4.w = fmaf(wx, fmaf(wz, db23.y, vb23.y), w0 * fmaf(wz, da23.y, va23.y));

        __stcs(aff + tid, a4);
        __stcs(res + tid, fmaf(a4.x, r0, fmaf(a4.y, g0, fmaf(a4.z, b0, a4.w))));
    }

    // ================= element 1 =================
    if (has1) {
        float gray = 0.299f * r1 + 0.587f * g1 + 0.114f * b1;
        float gz = __saturatef(gray) * 7.0f;
        float fz = floorf(gz);
        float wz = gz - fz;
        int z0 = (int)fz;

        float4 xe = xtab[q1];
        float wx  = xe.x;
        int zc = z0 * 3 + c;
        uint4 ua = slabh[__float_as_int(xe.y) + zc];
        uint4 ub = slabh[__float_as_int(xe.z) + zc];

        float w0 = 1.0f - wx;
        float2 va01 = h2f(ua.x), va23 = h2f(ua.y);
        float2 da01 = h2f(ua.z), da23 = h2f(ua.w);
        float2 vb01 = h2f(ub.x), vb23 = h2f(ub.y);
        float2 db01 = h2f(ub.z), db23 = h2f(ub.w);
        float4 a4;
        a4.x = fmaf(wx, fmaf(wz, db01.x, vb01.x), w0 * fmaf(wz, da01.x, va01.x));
        a4.y = fmaf(wx, fmaf(wz, db01.y, vb01.y), w0 * fmaf(wz, da01.y, va01.y));
        a4.z = fmaf(wx, fmaf(wz, db23.x, vb23.x), w0 * fmaf(wz, da23.x, va23.x));
        a4.w = fmaf(wx, fmaf(wz, db23.y, vb23.y), w0 * fmaf(wz, da23.y, va23.y));

        __stcs(aff + tid + BX, a4);
        __stcs(res + tid + BX, fmaf(a4.x, r1, fmaf(a4.y, g1, fmaf(a4.z, b1, a4.w))));
    }
}

extern "C" void kernel_launch(void* const* d_in, const int* in_sizes, int n_in,
                              void* d_out, int out_size) {
    const float* rgb   = (const float*)d_in[0];
    const float* grids = (const float*)d_in[1];
    const int*   idx   = (const int*)d_in[2];
    float* out = (float*)d_out;

    dim3 grid((W_IMG + PXB - 1) / PXB, H_IMG);   // 8 x 1080
    bilateral_grid_kernel<<<grid, BX>>>(rgb, grids, idx, out);
}